// round 1
// baseline (speedup 1.0000x reference)
#include <cuda_runtime.h>
#include <cuda_bf16.h>
#include <cstdint>

// Problem constants
#define NN 16384
#define DD 1024
#define CC 1024
#define EPSV 1e-6f
#define DEN_EPS 1e-5f

// ---------------- device scratch (static __device__ globals: allowed) ------
__device__ __nv_bfloat16 g_fb[NN * DD];     // features bf16  (32 MB)
__device__ __nv_bfloat16 g_cb[CC * DD];     // centers  bf16  ( 2 MB)
__device__ float g_rowterm[NN];
__device__ float g_centerterm[CC];
__device__ int   g_minmap[NN];              // order-preserving int-mapped float mins
__device__ float g_psum[64];
__device__ float g_pcnt[64];
__device__ int   g_odd_nonzero;             // labels dtype detection

// ---------------- helpers ---------------------------------------------------
__device__ __forceinline__ int fmap(float f) {
    int i = __float_as_int(f);
    return i >= 0 ? i : (i ^ 0x7FFFFFFF);
}
__device__ __forceinline__ float funmap(int i) {
    return __int_as_float(i >= 0 ? i : (i ^ 0x7FFFFFFF));
}

__device__ __forceinline__ void cp16(void* dst, const void* src) {
    unsigned d = (unsigned)__cvta_generic_to_shared(dst);
    asm volatile("cp.async.cg.shared.global [%0], [%1], 16;\n" :: "r"(d), "l"(src) : "memory");
}
__device__ __forceinline__ void cp_commit() {
    asm volatile("cp.async.commit_group;\n" ::: "memory");
}
__device__ __forceinline__ void cp_wait_all() {
    asm volatile("cp.async.wait_group 0;\n" ::: "memory");
}

__device__ __forceinline__ void ldm_x4(uint32_t* r, const void* p) {
    unsigned s = (unsigned)__cvta_generic_to_shared(p);
    asm volatile("ldmatrix.sync.aligned.m8n8.x4.shared.b16 {%0,%1,%2,%3}, [%4];\n"
                 : "=r"(r[0]), "=r"(r[1]), "=r"(r[2]), "=r"(r[3]) : "r"(s));
}

__device__ __forceinline__ void mma16816(float* c, const uint32_t* a,
                                         uint32_t b0, uint32_t b1) {
    asm volatile(
        "mma.sync.aligned.m16n8k16.row.col.f32.bf16.bf16.f32 "
        "{%0,%1,%2,%3}, {%4,%5,%6,%7}, {%8,%9}, {%0,%1,%2,%3};\n"
        : "+f"(c[0]), "+f"(c[1]), "+f"(c[2]), "+f"(c[3])
        : "r"(a[0]), "r"(a[1]), "r"(a[2]), "r"(a[3]), "r"(b0), "r"(b1));
}

// ---------------- prep: fp32 -> bf16 conversion + row terms ----------------
// One CTA (256 threads) per row of D=1024 floats.
__device__ __forceinline__ void prep_row(const float* __restrict__ src,
                                         __nv_bfloat16* dst, float* term,
                                         float coef, float add) {
    int row = blockIdx.x;
    int t = threadIdx.x;
    const float4* s4 = reinterpret_cast<const float4*>(src + (size_t)row * DD);
    float4 v = s4[t];

    __nv_bfloat162 lo = __floats2bfloat162_rn(v.x, v.y);
    __nv_bfloat162 hi = __floats2bfloat162_rn(v.z, v.w);
    uint2 packed;
    packed.x = *reinterpret_cast<uint32_t*>(&lo);
    packed.y = *reinterpret_cast<uint32_t*>(&hi);
    reinterpret_cast<uint2*>(dst + (size_t)row * DD)[t] = packed;

    float s  = v.x + v.y + v.z + v.w;
    float s2 = v.x * v.x + v.y * v.y + v.z * v.z + v.w * v.w;
    #pragma unroll
    for (int off = 16; off; off >>= 1) {
        s  += __shfl_xor_sync(0xffffffff, s,  off);
        s2 += __shfl_xor_sync(0xffffffff, s2, off);
    }
    __shared__ float sh[2][8];
    int w = t >> 5, l = t & 31;
    if (l == 0) { sh[0][w] = s; sh[1][w] = s2; }
    __syncthreads();
    if (t == 0) {
        float ts = 0.f, ts2 = 0.f;
        #pragma unroll
        for (int i = 0; i < 8; i++) { ts += sh[0][i]; ts2 += sh[1][i]; }
        term[row] = ts2 + coef * ts + add;
    }
}

__global__ void prep_features_kernel(const float* __restrict__ f) {
    prep_row(f, g_fb, g_rowterm, 2.0f * EPSV, EPSV * EPSV * (float)DD);
}
__global__ void prep_centers_kernel(const float* __restrict__ c) {
    prep_row(c, g_cb, g_centerterm, -2.0f * EPSV, 0.0f);
}

// ---------------- init ------------------------------------------------------
__global__ void init_kernel() {
    int i = blockIdx.x * blockDim.x + threadIdx.x;
    if (i < NN) g_minmap[i] = 0x7F800000;   // fmap(+inf)
    if (i == 0) g_odd_nonzero = 0;
}

// labels dtype sniff: if int64, every high 32-bit word (odd index) is zero.
__global__ void detect_kernel(const unsigned int* __restrict__ lw) {
    int i = blockIdx.x * blockDim.x + threadIdx.x;
    if (i < NN && (i & 1) && lw[i] != 0u) atomicOr(&g_odd_nonzero, 1);
}

// ---------------- GEMM + min epilogue --------------------------------------
// CTA tile 128x128, K tile 32, 8 warps in a 4(m) x 2(n) grid, warp tile 32x64.
#define BM 128
#define BN 128
#define BK 32
#define SK 40   // padded bf16 row stride (80B): conflict-free ldmatrix phases

__global__ void __launch_bounds__(256) gemm_min_kernel() {
    __shared__ __nv_bfloat16 As[2][BM][SK];
    __shared__ __nv_bfloat16 Bs[2][BN][SK];

    const int tid  = threadIdx.x;
    const int lane = tid & 31;
    const int wid  = tid >> 5;
    const int wm   = wid & 3;
    const int wn   = wid >> 2;
    const int brow = blockIdx.y * BM;   // feature rows
    const int bcol = blockIdx.x * BN;   // center rows

    const __nv_bfloat16* Ag = g_fb + (size_t)brow * DD;
    const __nv_bfloat16* Bg = g_cb + (size_t)bcol * DD;

    float acc[2][8][4];
    #pragma unroll
    for (int mt = 0; mt < 2; mt++)
        #pragma unroll
        for (int nt = 0; nt < 8; nt++)
            #pragma unroll
            for (int j = 0; j < 4; j++) acc[mt][nt][j] = 0.f;

    // stage loader: 512 16B chunks per operand, 2 per thread
    auto stage = [&](int kt, int buf) {
        int k0 = kt * BK;
        #pragma unroll
        for (int i = 0; i < 2; i++) {
            int c  = tid + i * 256;
            int r  = c >> 2;
            int cb = c & 3;
            cp16(&As[buf][r][cb * 8], Ag + r * DD + k0 + cb * 8);
            cp16(&Bs[buf][r][cb * 8], Bg + r * DD + k0 + cb * 8);
        }
        cp_commit();
    };

    stage(0, 0);
    int buf = 0;
    const int NK = DD / BK;   // 32
    for (int kt = 0; kt < NK; kt++) {
        cp_wait_all();
        __syncthreads();
        if (kt + 1 < NK) stage(kt + 1, buf ^ 1);

        #pragma unroll
        for (int ks = 0; ks < 2; ks++) {
            uint32_t a[2][4];
            #pragma unroll
            for (int mt = 0; mt < 2; mt++) {
                int r   = wm * 32 + mt * 16 + (lane & 15);
                int col = ks * 16 + ((lane >> 4) << 3);
                ldm_x4(a[mt], &As[buf][r][col]);
            }
            uint32_t b[4][4];
            #pragma unroll
            for (int p = 0; p < 4; p++) {
                int nloc = (lane & 7) + ((lane & 16) >> 1);
                int koff = ks * 16 + (((lane >> 3) & 1) << 3);
                ldm_x4(b[p], &Bs[buf][wn * 64 + p * 16 + nloc][koff]);
            }
            #pragma unroll
            for (int mt = 0; mt < 2; mt++)
                #pragma unroll
                for (int p = 0; p < 4; p++) {
                    mma16816(acc[mt][2 * p],     a[mt], b[p][0], b[p][1]);
                    mma16816(acc[mt][2 * p + 1], a[mt], b[p][2], b[p][3]);
                }
        }
        buf ^= 1;
    }

    // epilogue: min over this CTA's 128 columns of (centerterm - 2*S)
    const float* ct = g_centerterm + bcol + wn * 64;
    #pragma unroll
    for (int mt = 0; mt < 2; mt++) {
        float m0 = 1e30f, m1 = 1e30f;
        #pragma unroll
        for (int nt = 0; nt < 8; nt++) {
            float c0 = ct[nt * 8 + (lane & 3) * 2];
            float c1 = ct[nt * 8 + (lane & 3) * 2 + 1];
            m0 = fminf(m0, fminf(c0 - 2.f * acc[mt][nt][0], c1 - 2.f * acc[mt][nt][1]));
            m1 = fminf(m1, fminf(c0 - 2.f * acc[mt][nt][2], c1 - 2.f * acc[mt][nt][3]));
        }
        #pragma unroll
        for (int off = 1; off < 4; off <<= 1) {
            m0 = fminf(m0, __shfl_xor_sync(0xffffffff, m0, off));
            m1 = fminf(m1, __shfl_xor_sync(0xffffffff, m1, off));
        }
        if ((lane & 3) == 0) {
            int r = brow + wm * 32 + mt * 16 + (lane >> 2);
            atomicMin(&g_minmap[r],     fmap(m0));
            atomicMin(&g_minmap[r + 8], fmap(m1));
        }
    }
}

// ---------------- masked reduction ------------------------------------------
__global__ void reduce_kernel(const void* __restrict__ labels) {
    int b   = blockIdx.x;            // 64 blocks x 256 threads = 16384 rows
    int row = b * 256 + threadIdx.x;

    float m    = funmap(g_minmap[row]);
    float sq   = g_rowterm[row] + m;
    float dist = sqrtf(fmaxf(sq, 0.f));

    long long lab;
    if (g_odd_nonzero == 0) lab = ((const long long*)labels)[row];   // int64
    else                    lab = ((const int*)labels)[row];         // int32
    float mask = (lab == 0) ? 1.f : 0.f;

    float s = dist * mask;
    float c = mask;
    #pragma unroll
    for (int off = 16; off; off >>= 1) {
        s += __shfl_xor_sync(0xffffffff, s, off);
        c += __shfl_xor_sync(0xffffffff, c, off);
    }
    __shared__ float sh[2][8];
    int w = threadIdx.x >> 5, l = threadIdx.x & 31;
    if (l == 0) { sh[0][w] = s; sh[1][w] = c; }
    __syncthreads();
    if (threadIdx.x == 0) {
        float ts = 0.f, tc = 0.f;
        #pragma unroll
        for (int i = 0; i < 8; i++) { ts += sh[0][i]; tc += sh[1][i]; }
        g_psum[b] = ts;
        g_pcnt[b] = tc;
    }
}

__global__ void final_kernel(float* __restrict__ out) {
    int t = threadIdx.x;   // 32 threads
    float s = g_psum[t] + g_psum[t + 32];
    float c = g_pcnt[t] + g_pcnt[t + 32];
    #pragma unroll
    for (int off = 16; off; off >>= 1) {
        s += __shfl_xor_sync(0xffffffff, s, off);
        c += __shfl_xor_sync(0xffffffff, c, off);
    }
    if (t == 0) out[0] = s / (c + DEN_EPS);
}

// ---------------- launch -----------------------------------------------------
extern "C" void kernel_launch(void* const* d_in, const int* in_sizes, int n_in,
                              void* d_out, int out_size) {
    const float* features = (const float*)d_in[0];
    const void*  labels   = d_in[1];
    const float* centers  = (const float*)d_in[2];
    float* out = (float*)d_out;

    init_kernel<<<64, 256>>>();
    detect_kernel<<<64, 256>>>((const unsigned int*)labels);
    prep_features_kernel<<<NN, 256>>>(features);
    prep_centers_kernel<<<CC, 256>>>(centers);
    gemm_min_kernel<<<dim3(CC / BN, NN / BM), 256>>>();
    reduce_kernel<<<64, 256>>>(labels);
    final_kernel<<<1, 32>>>(out);
}

// round 3
// speedup vs baseline: 1.1202x; 1.1202x over previous
#include <cuda_runtime.h>
#include <cuda_bf16.h>
#include <cstdint>

// Problem constants
#define NN 16384
#define DD 1024
#define CC 1024
#define EPSV 1e-6f
#define DEN_EPS 1e-5f

// ---------------- device scratch ---------------------------------------------
__device__ __align__(1024) __nv_bfloat16 g_fb[NN * DD];   // features bf16 (32MB)
__device__ __align__(1024) __nv_bfloat16 g_cb[CC * DD];   // centers  bf16 ( 2MB)
__device__ float g_rowterm[NN];
__device__ float g_centerterm[CC];
__device__ int   g_minmap[NN];
__device__ float g_psum[64];
__device__ float g_pcnt[64];
__device__ int   g_odd_nonzero = 0;

// ---------------- helpers -------------------------------------------------------
__device__ __forceinline__ int fmap(float f) {
    int i = __float_as_int(f);
    return i >= 0 ? i : (i ^ 0x7FFFFFFF);
}
__device__ __forceinline__ float funmap(int i) {
    return __int_as_float(i >= 0 ? i : (i ^ 0x7FFFFFFF));
}

__device__ __forceinline__ void cp16(void* dst, const void* src) {
    unsigned d = (unsigned)__cvta_generic_to_shared(dst);
    asm volatile("cp.async.cg.shared.global [%0], [%1], 16;\n" :: "r"(d), "l"(src) : "memory");
}
__device__ __forceinline__ void cp_commit() {
    asm volatile("cp.async.commit_group;\n" ::: "memory");
}
template <int N>
__device__ __forceinline__ void cp_wait() {
    asm volatile("cp.async.wait_group %0;\n" :: "n"(N) : "memory");
}

__device__ __forceinline__ void ldm_x4(uint32_t* r, const void* p) {
    unsigned s = (unsigned)__cvta_generic_to_shared(p);
    asm volatile("ldmatrix.sync.aligned.m8n8.x4.shared.b16 {%0,%1,%2,%3}, [%4];\n"
                 : "=r"(r[0]), "=r"(r[1]), "=r"(r[2]), "=r"(r[3]) : "r"(s));
}

__device__ __forceinline__ void mma16816(float* c, const uint32_t* a,
                                         uint32_t b0, uint32_t b1) {
    asm volatile(
        "mma.sync.aligned.m16n8k16.row.col.f32.bf16.bf16.f32 "
        "{%0,%1,%2,%3}, {%4,%5,%6,%7}, {%8,%9}, {%0,%1,%2,%3};\n"
        : "+f"(c[0]), "+f"(c[1]), "+f"(c[2]), "+f"(c[3])
        : "r"(a[0]), "r"(a[1]), "r"(a[2]), "r"(a[3]), "r"(b0), "r"(b1));
}

// ---------------- prep: fp32 -> bf16 + row terms (1 warp per row) ---------------
__device__ __forceinline__ void prep_rows(const float* __restrict__ src,
                                          __nv_bfloat16* dst, float* term,
                                          float coef, float add) {
    int wid  = threadIdx.x >> 5;
    int lane = threadIdx.x & 31;
    int row  = blockIdx.x * 8 + wid;

    const float4* s4 = reinterpret_cast<const float4*>(src + (size_t)row * DD);
    uint2* d2 = reinterpret_cast<uint2*>(dst + (size_t)row * DD);

    float s = 0.f, s2 = 0.f;
    #pragma unroll
    for (int i = 0; i < 8; i++) {
        float4 v = s4[i * 32 + lane];
        __nv_bfloat162 lo = __floats2bfloat162_rn(v.x, v.y);
        __nv_bfloat162 hi = __floats2bfloat162_rn(v.z, v.w);
        uint2 packed;
        packed.x = *reinterpret_cast<uint32_t*>(&lo);
        packed.y = *reinterpret_cast<uint32_t*>(&hi);
        d2[i * 32 + lane] = packed;
        s  += v.x + v.y + v.z + v.w;
        s2 += v.x * v.x + v.y * v.y + v.z * v.z + v.w * v.w;
    }
    #pragma unroll
    for (int off = 16; off; off >>= 1) {
        s  += __shfl_xor_sync(0xffffffff, s,  off);
        s2 += __shfl_xor_sync(0xffffffff, s2, off);
    }
    if (lane == 0) term[row] = s2 + coef * s + add;
}

__global__ void __launch_bounds__(256) prep_features_kernel(const float* __restrict__ f) {
    prep_rows(f, g_fb, g_rowterm, 2.0f * EPSV, EPSV * EPSV * (float)DD);
}
__global__ void __launch_bounds__(256) prep_centers_kernel(const float* __restrict__ c) {
    prep_rows(c, g_cb, g_centerterm, -2.0f * EPSV, 0.0f);
}

// ---------------- init + labels dtype detect ------------------------------------
__global__ void detect_init_kernel(const unsigned int* __restrict__ lw) {
    int i = blockIdx.x * blockDim.x + threadIdx.x;
    g_minmap[i] = 0x7F800000;
    if ((i & 1) && lw[i] != 0u) atomicOr(&g_odd_nonzero, 1);
}

// ---------------- GEMM + min epilogue --------------------------------------------
// CTA tile 128(M) x 256(N), BK=64, 3-stage cp.async pipeline.
// 8 warps: 2(m) x 4(n), warp tile 64x64. SW128 swizzled smem (128B rows).
#define BM 128
#define BN 256
#define BK 64
#define NK (DD / BK)            // 16
#define A_BYTES (BM * BK * 2)   // 16384
#define B_BYTES (BN * BK * 2)   // 32768
#define STAGE_BYTES (A_BYTES + B_BYTES)
#define STAGES 3
#define GEMM_SMEM (STAGES * STAGE_BYTES + 1024 + 16)

// swizzled byte offset for (row, kbyte) in a 128B-row tile
__device__ __forceinline__ uint32_t swz(int r, int kbyte) {
    return (uint32_t)(r * 128 + (((kbyte >> 4) ^ (r & 7)) << 4) + (kbyte & 15));
}

__global__ void __launch_bounds__(256, 1) gemm_min_kernel() {
    extern __shared__ char sm_raw[];
    char* smb = sm_raw;                       // stages
    float* cterm = (float*)(sm_raw + STAGES * STAGE_BYTES);  // 256 floats

    const int tid  = threadIdx.x;
    const int lane = tid & 31;
    const int wid  = tid >> 5;
    const int wm   = wid >> 2;       // 0..1
    const int wn   = wid & 3;        // 0..3
    const int brow = blockIdx.y * BM;
    const int bcol = blockIdx.x * BN;

    const __nv_bfloat16* Ag = g_fb + (size_t)brow * DD;
    const __nv_bfloat16* Bg = g_cb + (size_t)bcol * DD;

    cterm[tid] = g_centerterm[bcol + tid];

    float acc[4][8][4];
    #pragma unroll
    for (int mt = 0; mt < 4; mt++)
        #pragma unroll
        for (int nt = 0; nt < 8; nt++)
            #pragma unroll
            for (int j = 0; j < 4; j++) acc[mt][nt][j] = 0.f;

    // stage loader: A 1024 chunks + B 2048 chunks of 16B, 12 per thread
    auto stage = [&](int kt, int buf) {
        int k0 = kt * BK;
        char* As = smb + buf * STAGE_BYTES;
        char* Bs = As + A_BYTES;
        #pragma unroll
        for (int i = 0; i < 4; i++) {
            int idx = tid + i * 256;
            int r = idx >> 3, c = idx & 7;
            cp16(As + swz(r, c * 16), Ag + (size_t)r * DD + k0 + c * 8);
        }
        #pragma unroll
        for (int i = 0; i < 8; i++) {
            int idx = tid + i * 256;
            int r = idx >> 3, c = idx & 7;
            cp16(Bs + swz(r, c * 16), Bg + (size_t)r * DD + k0 + c * 8);
        }
        cp_commit();
    };

    stage(0, 0);
    stage(1, 1);

    for (int kt = 0; kt < NK; kt++) {
        if (kt < NK - 1) cp_wait<1>(); else cp_wait<0>();
        __syncthreads();
        if (kt + 2 < NK) stage(kt + 2, (kt + 2) % STAGES);

        char* As = smb + (kt % STAGES) * STAGE_BYTES;
        char* Bs = As + A_BYTES;

        #pragma unroll
        for (int ks = 0; ks < 4; ks++) {   // 4 x k16
            uint32_t a[4][4];
            #pragma unroll
            for (int mt = 0; mt < 4; mt++) {
                int r = wm * 64 + mt * 16 + (lane & 15);
                int kbyte = ks * 32 + ((lane >> 4) << 4);
                ldm_x4(a[mt], As + swz(r, kbyte));
            }
            uint32_t b[4][4];
            #pragma unroll
            for (int p = 0; p < 4; p++) {
                int r = wn * 64 + p * 16 + (lane & 7) + ((lane & 16) >> 1);
                int kbyte = ks * 32 + (((lane >> 3) & 1) << 4);
                ldm_x4(b[p], Bs + swz(r, kbyte));
            }
            #pragma unroll
            for (int mt = 0; mt < 4; mt++)
                #pragma unroll
                for (int p = 0; p < 4; p++) {
                    mma16816(acc[mt][2 * p],     a[mt], b[p][0], b[p][1]);
                    mma16816(acc[mt][2 * p + 1], a[mt], b[p][2], b[p][3]);
                }
        }
    }

    // ---- epilogue: min over this CTA's 256 columns of (centerterm - 2*S) ----
    const float* ct = cterm + wn * 64;
    #pragma unroll
    for (int mt = 0; mt < 4; mt++) {
        float m0 = 1e30f, m1 = 1e30f;
        #pragma unroll
        for (int nt = 0; nt < 8; nt++) {
            float c0 = ct[nt * 8 + (lane & 3) * 2];
            float c1 = ct[nt * 8 + (lane & 3) * 2 + 1];
            m0 = fminf(m0, fminf(fmaf(-2.f, acc[mt][nt][0], c0),
                                 fmaf(-2.f, acc[mt][nt][1], c1)));
            m1 = fminf(m1, fminf(fmaf(-2.f, acc[mt][nt][2], c0),
                                 fmaf(-2.f, acc[mt][nt][3], c1)));
        }
        #pragma unroll
        for (int off = 1; off < 4; off <<= 1) {
            m0 = fminf(m0, __shfl_xor_sync(0xffffffff, m0, off));
            m1 = fminf(m1, __shfl_xor_sync(0xffffffff, m1, off));
        }
        if ((lane & 3) == 0) {
            int r = brow + wm * 64 + mt * 16 + (lane >> 2);
            atomicMin(&g_minmap[r],     fmap(m0));
            atomicMin(&g_minmap[r + 8], fmap(m1));
        }
    }
}

// ---------------- masked reduction ------------------------------------------------
__global__ void reduce_kernel(const void* __restrict__ labels) {
    int b   = blockIdx.x;
    int row = b * 256 + threadIdx.x;

    float m    = funmap(g_minmap[row]);
    float sq   = g_rowterm[row] + m;
    float dist = sqrtf(fmaxf(sq, 0.f));

    long long lab;
    if (g_odd_nonzero == 0) lab = ((const long long*)labels)[row];   // int64
    else                    lab = ((const int*)labels)[row];         // int32
    float mask = (lab == 0) ? 1.f : 0.f;

    float s = dist * mask;
    float c = mask;
    #pragma unroll
    for (int off = 16; off; off >>= 1) {
        s += __shfl_xor_sync(0xffffffff, s, off);
        c += __shfl_xor_sync(0xffffffff, c, off);
    }
    __shared__ float sh[2][8];
    int w = threadIdx.x >> 5, l = threadIdx.x & 31;
    if (l == 0) { sh[0][w] = s; sh[1][w] = c; }
    __syncthreads();
    if (threadIdx.x == 0) {
        float ts = 0.f, tc = 0.f;
        #pragma unroll
        for (int i = 0; i < 8; i++) { ts += sh[0][i]; tc += sh[1][i]; }
        g_psum[b] = ts;
        g_pcnt[b] = tc;
    }
}

__global__ void final_kernel(float* __restrict__ out) {
    int t = threadIdx.x;
    float s = g_psum[t] + g_psum[t + 32];
    float c = g_pcnt[t] + g_pcnt[t + 32];
    #pragma unroll
    for (int off = 16; off; off >>= 1) {
        s += __shfl_xor_sync(0xffffffff, s, off);
        c += __shfl_xor_sync(0xffffffff, c, off);
    }
    if (t == 0) out[0] = s / (c + DEN_EPS);
}

// ---------------- launch -------------------------------------------------------------
extern "C" void kernel_launch(void* const* d_in, const int* in_sizes, int n_in,
                              void* d_out, int out_size) {
    const float* features = (const float*)d_in[0];
    const void*  labels   = d_in[1];
    const float* centers  = (const float*)d_in[2];
    float* out = (float*)d_out;

    cudaFuncSetAttribute(gemm_min_kernel,
                         cudaFuncAttributeMaxDynamicSharedMemorySize, GEMM_SMEM);

    detect_init_kernel<<<64, 256>>>((const unsigned int*)labels);
    prep_features_kernel<<<NN / 8, 256>>>(features);
    prep_centers_kernel<<<CC / 8, 256>>>(centers);
    gemm_min_kernel<<<dim3(CC / BN, NN / BM), 256, GEMM_SMEM>>>();
    reduce_kernel<<<64, 256>>>(labels);
    final_kernel<<<1, 32>>>(out);
}

// round 4
// speedup vs baseline: 1.2573x; 1.1223x over previous
#include <cuda_runtime.h>
#include <cuda_bf16.h>
#include <cstdint>

// Problem constants
#define NN 16384
#define DD 1024
#define CC 1024
#define EPSV 1e-6f
#define DEN_EPS 1e-5f

// ---------------- device scratch ---------------------------------------------
__device__ __align__(1024) __nv_bfloat16 g_fb[NN * DD];   // features bf16 (32MB)
__device__ __align__(1024) __nv_bfloat16 g_cb[CC * DD];   // centers  bf16 ( 2MB)
__device__ float g_rowterm[NN];
__device__ float g_centerterm[CC];
__device__ int   g_minmap[NN];
__device__ float g_psum[64];
__device__ float g_pcnt[64];
__device__ int   g_odd_nonzero = 0;

// ---------------- helpers -------------------------------------------------------
__device__ __forceinline__ int fmap(float f) {
    int i = __float_as_int(f);
    return i >= 0 ? i : (i ^ 0x7FFFFFFF);
}
__device__ __forceinline__ float funmap(int i) {
    return __int_as_float(i >= 0 ? i : (i ^ 0x7FFFFFFF));
}

__device__ __forceinline__ void cp16(void* dst, const void* src) {
    unsigned d = (unsigned)__cvta_generic_to_shared(dst);
    asm volatile("cp.async.cg.shared.global [%0], [%1], 16;\n" :: "r"(d), "l"(src) : "memory");
}
__device__ __forceinline__ void cp_commit() {
    asm volatile("cp.async.commit_group;\n" ::: "memory");
}
template <int N>
__device__ __forceinline__ void cp_wait() {
    asm volatile("cp.async.wait_group %0;\n" :: "n"(N) : "memory");
}

__device__ __forceinline__ void ldm_x4(uint32_t* r, const void* p) {
    unsigned s = (unsigned)__cvta_generic_to_shared(p);
    asm volatile("ldmatrix.sync.aligned.m8n8.x4.shared.b16 {%0,%1,%2,%3}, [%4];\n"
                 : "=r"(r[0]), "=r"(r[1]), "=r"(r[2]), "=r"(r[3]) : "r"(s));
}

__device__ __forceinline__ void mma16816(float* c, const uint32_t* a,
                                         uint32_t b0, uint32_t b1) {
    asm volatile(
        "mma.sync.aligned.m16n8k16.row.col.f32.bf16.bf16.f32 "
        "{%0,%1,%2,%3}, {%4,%5,%6,%7}, {%8,%9}, {%0,%1,%2,%3};\n"
        : "+f"(c[0]), "+f"(c[1]), "+f"(c[2]), "+f"(c[3])
        : "r"(a[0]), "r"(a[1]), "r"(a[2]), "r"(a[3]), "r"(b0), "r"(b1));
}

// ---------------- prep: fp32 -> bf16 + row terms (1 warp per row) ---------------
__device__ __forceinline__ void prep_rows(const float* __restrict__ src,
                                          __nv_bfloat16* dst, float* term,
                                          float coef, float add) {
    int wid  = threadIdx.x >> 5;
    int lane = threadIdx.x & 31;
    int row  = blockIdx.x * 8 + wid;

    const float4* s4 = reinterpret_cast<const float4*>(src + (size_t)row * DD);
    uint2* d2 = reinterpret_cast<uint2*>(dst + (size_t)row * DD);

    float s = 0.f, s2 = 0.f;
    #pragma unroll
    for (int i = 0; i < 8; i++) {
        float4 v = s4[i * 32 + lane];
        __nv_bfloat162 lo = __floats2bfloat162_rn(v.x, v.y);
        __nv_bfloat162 hi = __floats2bfloat162_rn(v.z, v.w);
        uint2 packed;
        packed.x = *reinterpret_cast<uint32_t*>(&lo);
        packed.y = *reinterpret_cast<uint32_t*>(&hi);
        d2[i * 32 + lane] = packed;
        s  += v.x + v.y + v.z + v.w;
        s2 += v.x * v.x + v.y * v.y + v.z * v.z + v.w * v.w;
    }
    #pragma unroll
    for (int off = 16; off; off >>= 1) {
        s  += __shfl_xor_sync(0xffffffff, s,  off);
        s2 += __shfl_xor_sync(0xffffffff, s2, off);
    }
    if (lane == 0) term[row] = s2 + coef * s + add;
}

__global__ void __launch_bounds__(256) prep_features_kernel(const float* __restrict__ f) {
    prep_rows(f, g_fb, g_rowterm, 2.0f * EPSV, EPSV * EPSV * (float)DD);
}
__global__ void __launch_bounds__(256) prep_centers_kernel(const float* __restrict__ c) {
    prep_rows(c, g_cb, g_centerterm, -2.0f * EPSV, 0.0f);
}

// ---------------- init + labels dtype detect ------------------------------------
__global__ void detect_init_kernel(const unsigned int* __restrict__ lw) {
    int i = blockIdx.x * blockDim.x + threadIdx.x;
    g_minmap[i] = 0x7F800000;
    if ((i & 1) && lw[i] != 0u) atomicOr(&g_odd_nonzero, 1);
}

// ---------------- GEMM + min epilogue --------------------------------------------
// CTA tile 128(M) x 128(N), BK=64, 3-stage cp.async pipeline, 2 CTAs/SM.
// 8 warps: 2(m) x 4(n), warp tile 64x32. SW128 swizzled smem (128B rows).
#define BM 128
#define BN 128
#define BK 64
#define NK (DD / BK)            // 16
#define A_BYTES (BM * BK * 2)   // 16384
#define B_BYTES (BN * BK * 2)   // 16384
#define STAGE_BYTES (A_BYTES + B_BYTES)
#define STAGES 3
#define GEMM_SMEM (STAGES * STAGE_BYTES + 512 + 16)

// swizzled byte offset for (row, kbyte) in a 128B-row tile
__device__ __forceinline__ uint32_t swz(int r, int kbyte) {
    return (uint32_t)(r * 128 + (((kbyte >> 4) ^ (r & 7)) << 4) + (kbyte & 15));
}

__global__ void __launch_bounds__(256, 2) gemm_min_kernel() {
    extern __shared__ char sm_raw[];
    char* smb = sm_raw;
    float* cterm = (float*)(sm_raw + STAGES * STAGE_BYTES);  // 128 floats

    const int tid  = threadIdx.x;
    const int lane = tid & 31;
    const int wid  = tid >> 5;
    const int wm   = wid >> 2;       // 0..1
    const int wn   = wid & 3;        // 0..3
    const int brow = blockIdx.y * BM;
    const int bcol = blockIdx.x * BN;

    const __nv_bfloat16* Ag = g_fb + (size_t)brow * DD;
    const __nv_bfloat16* Bg = g_cb + (size_t)bcol * DD;

    if (tid < BN) cterm[tid] = g_centerterm[bcol + tid];

    float acc[4][4][4];   // mt x p x 4
    #pragma unroll
    for (int mt = 0; mt < 4; mt++)
        #pragma unroll
        for (int p = 0; p < 4; p++)
            #pragma unroll
            for (int j = 0; j < 4; j++) acc[mt][p][j] = 0.f;

    // stage loader: A 1024 + B 1024 chunks of 16B, 8 per thread
    auto stage = [&](int kt, int buf) {
        int k0 = kt * BK;
        char* As = smb + buf * STAGE_BYTES;
        char* Bs = As + A_BYTES;
        #pragma unroll
        for (int i = 0; i < 4; i++) {
            int idx = tid + i * 256;
            int r = idx >> 3, c = idx & 7;
            cp16(As + swz(r, c * 16), Ag + (size_t)r * DD + k0 + c * 8);
        }
        #pragma unroll
        for (int i = 0; i < 4; i++) {
            int idx = tid + i * 256;
            int r = idx >> 3, c = idx & 7;
            cp16(Bs + swz(r, c * 16), Bg + (size_t)r * DD + k0 + c * 8);
        }
        cp_commit();
    };

    stage(0, 0);
    stage(1, 1);

    for (int kt = 0; kt < NK; kt++) {
        if (kt < NK - 1) cp_wait<1>(); else cp_wait<0>();
        __syncthreads();
        if (kt + 2 < NK) stage(kt + 2, (kt + 2) % STAGES);

        char* As = smb + (kt % STAGES) * STAGE_BYTES;
        char* Bs = As + A_BYTES;

        #pragma unroll
        for (int ks = 0; ks < 4; ks++) {   // 4 x k16
            uint32_t a[4][4];
            #pragma unroll
            for (int mt = 0; mt < 4; mt++) {
                int r = wm * 64 + mt * 16 + (lane & 15);
                int kbyte = ks * 32 + ((lane >> 4) << 4);
                ldm_x4(a[mt], As + swz(r, kbyte));
            }
            uint32_t b[2][4];
            #pragma unroll
            for (int p = 0; p < 2; p++) {
                int r = wn * 32 + p * 16 + (lane & 7) + ((lane & 16) >> 1);
                int kbyte = ks * 32 + (((lane >> 3) & 1) << 4);
                ldm_x4(b[p], Bs + swz(r, kbyte));
            }
            #pragma unroll
            for (int mt = 0; mt < 4; mt++)
                #pragma unroll
                for (int p = 0; p < 2; p++) {
                    mma16816(acc[mt][2 * p],     a[mt], b[p][0], b[p][1]);
                    mma16816(acc[mt][2 * p + 1], a[mt], b[p][2], b[p][3]);
                }
        }
    }

    // ---- epilogue: min over this CTA's 128 columns of (centerterm - 2*S) ----
    const float* ct = cterm + wn * 32;
    #pragma unroll
    for (int mt = 0; mt < 4; mt++) {
        float m0 = 1e30f, m1 = 1e30f;
        #pragma unroll
        for (int p = 0; p < 4; p++) {
            float c0 = ct[p * 8 + (lane & 3) * 2];
            float c1 = ct[p * 8 + (lane & 3) * 2 + 1];
            m0 = fminf(m0, fminf(fmaf(-2.f, acc[mt][p][0], c0),
                                 fmaf(-2.f, acc[mt][p][1], c1)));
            m1 = fminf(m1, fminf(fmaf(-2.f, acc[mt][p][2], c0),
                                 fmaf(-2.f, acc[mt][p][3], c1)));
        }
        #pragma unroll
        for (int off = 1; off < 4; off <<= 1) {
            m0 = fminf(m0, __shfl_xor_sync(0xffffffff, m0, off));
            m1 = fminf(m1, __shfl_xor_sync(0xffffffff, m1, off));
        }
        if ((lane & 3) == 0) {
            int r = brow + wm * 64 + mt * 16 + (lane >> 2);
            atomicMin(&g_minmap[r],     fmap(m0));
            atomicMin(&g_minmap[r + 8], fmap(m1));
        }
    }
}

// ---------------- masked reduction ------------------------------------------------
__global__ void reduce_kernel(const void* __restrict__ labels) {
    int b   = blockIdx.x;
    int row = b * 256 + threadIdx.x;

    float m    = funmap(g_minmap[row]);
    float sq   = g_rowterm[row] + m;
    float dist = sqrtf(fmaxf(sq, 0.f));

    long long lab;
    if (g_odd_nonzero == 0) lab = ((const long long*)labels)[row];   // int64
    else                    lab = ((const int*)labels)[row];         // int32
    float mask = (lab == 0) ? 1.f : 0.f;

    float s = dist * mask;
    float c = mask;
    #pragma unroll
    for (int off = 16; off; off >>= 1) {
        s += __shfl_xor_sync(0xffffffff, s, off);
        c += __shfl_xor_sync(0xffffffff, c, off);
    }
    __shared__ float sh[2][8];
    int w = threadIdx.x >> 5, l = threadIdx.x & 31;
    if (l == 0) { sh[0][w] = s; sh[1][w] = c; }
    __syncthreads();
    if (threadIdx.x == 0) {
        float ts = 0.f, tc = 0.f;
        #pragma unroll
        for (int i = 0; i < 8; i++) { ts += sh[0][i]; tc += sh[1][i]; }
        g_psum[b] = ts;
        g_pcnt[b] = tc;
    }
}

__global__ void final_kernel(float* __restrict__ out) {
    int t = threadIdx.x;
    float s = g_psum[t] + g_psum[t + 32];
    float c = g_pcnt[t] + g_pcnt[t + 32];
    #pragma unroll
    for (int off = 16; off; off >>= 1) {
        s += __shfl_xor_sync(0xffffffff, s, off);
        c += __shfl_xor_sync(0xffffffff, c, off);
    }
    if (t == 0) out[0] = s / (c + DEN_EPS);
}

// ---------------- launch -------------------------------------------------------------
extern "C" void kernel_launch(void* const* d_in, const int* in_sizes, int n_in,
                              void* d_out, int out_size) {
    const float* features = (const float*)d_in[0];
    const void*  labels   = d_in[1];
    const float* centers  = (const float*)d_in[2];
    float* out = (float*)d_out;

    cudaFuncSetAttribute(gemm_min_kernel,
                         cudaFuncAttributeMaxDynamicSharedMemorySize, GEMM_SMEM);

    detect_init_kernel<<<64, 256>>>((const unsigned int*)labels);
    prep_features_kernel<<<NN / 8, 256>>>(features);
    prep_centers_kernel<<<CC / 8, 256>>>(centers);
    gemm_min_kernel<<<dim3(CC / BN, NN / BM), 256, GEMM_SMEM>>>();
    reduce_kernel<<<64, 256>>>(labels);
    final_kernel<<<1, 32>>>(out);
}

// round 5
// speedup vs baseline: 1.2975x; 1.0319x over previous
#include <cuda_runtime.h>
#include <cuda_bf16.h>
#include <cstdint>

// Problem constants
#define NN 16384
#define DD 1024
#define CC 1024
#define EPSV 1e-6f
#define DEN_EPS 1e-5f

// ---------------- device scratch ---------------------------------------------
__device__ __align__(1024) __nv_bfloat16 g_fb[NN * DD];   // features bf16 (32MB)
__device__ __align__(1024) __nv_bfloat16 g_cb[CC * DD];   // centers  bf16 ( 2MB)
__device__ float g_rowterm[NN];
__device__ float g_centerterm[CC];
__device__ int   g_minmap[NN];
__device__ float g_psum[64];
__device__ float g_pcnt[64];
__device__ int   g_odd_nonzero = 0;

// ---------------- helpers -------------------------------------------------------
__device__ __forceinline__ int fmap(float f) {
    int i = __float_as_int(f);
    return i >= 0 ? i : (i ^ 0x7FFFFFFF);
}
__device__ __forceinline__ float funmap(int i) {
    return __int_as_float(i >= 0 ? i : (i ^ 0x7FFFFFFF));
}

__device__ __forceinline__ void cp16(void* dst, const void* src) {
    unsigned d = (unsigned)__cvta_generic_to_shared(dst);
    asm volatile("cp.async.cg.shared.global [%0], [%1], 16;\n" :: "r"(d), "l"(src) : "memory");
}
__device__ __forceinline__ void cp_commit() {
    asm volatile("cp.async.commit_group;\n" ::: "memory");
}
template <int N>
__device__ __forceinline__ void cp_wait() {
    asm volatile("cp.async.wait_group %0;\n" :: "n"(N) : "memory");
}

__device__ __forceinline__ void ldm_x4(uint32_t* r, const void* p) {
    unsigned s = (unsigned)__cvta_generic_to_shared(p);
    asm volatile("ldmatrix.sync.aligned.m8n8.x4.shared.b16 {%0,%1,%2,%3}, [%4];\n"
                 : "=r"(r[0]), "=r"(r[1]), "=r"(r[2]), "=r"(r[3]) : "r"(s));
}

__device__ __forceinline__ void mma16816(float* c, const uint32_t* a,
                                         uint32_t b0, uint32_t b1) {
    asm volatile(
        "mma.sync.aligned.m16n8k16.row.col.f32.bf16.bf16.f32 "
        "{%0,%1,%2,%3}, {%4,%5,%6,%7}, {%8,%9}, {%0,%1,%2,%3};\n"
        : "+f"(c[0]), "+f"(c[1]), "+f"(c[2]), "+f"(c[3])
        : "r"(a[0]), "r"(a[1]), "r"(a[2]), "r"(a[3]), "r"(b0), "r"(b1));
}

// ---------------- prep: fp32 -> bf16 + row terms (1 warp per row) ---------------
__device__ __forceinline__ void prep_rows(const float* __restrict__ src,
                                          __nv_bfloat16* dst, float* term,
                                          float coef, float add) {
    int wid  = threadIdx.x >> 5;
    int lane = threadIdx.x & 31;
    int row  = blockIdx.x * 8 + wid;

    const float4* s4 = reinterpret_cast<const float4*>(src + (size_t)row * DD);
    uint2* d2 = reinterpret_cast<uint2*>(dst + (size_t)row * DD);

    float s = 0.f, s2 = 0.f;
    #pragma unroll
    for (int i = 0; i < 8; i++) {
        float4 v = s4[i * 32 + lane];
        __nv_bfloat162 lo = __floats2bfloat162_rn(v.x, v.y);
        __nv_bfloat162 hi = __floats2bfloat162_rn(v.z, v.w);
        uint2 packed;
        packed.x = *reinterpret_cast<uint32_t*>(&lo);
        packed.y = *reinterpret_cast<uint32_t*>(&hi);
        d2[i * 32 + lane] = packed;
        s  += v.x + v.y + v.z + v.w;
        s2 += v.x * v.x + v.y * v.y + v.z * v.z + v.w * v.w;
    }
    #pragma unroll
    for (int off = 16; off; off >>= 1) {
        s  += __shfl_xor_sync(0xffffffff, s,  off);
        s2 += __shfl_xor_sync(0xffffffff, s2, off);
    }
    if (lane == 0) term[row] = s2 + coef * s + add;
}

__global__ void __launch_bounds__(256) prep_features_kernel(const float* __restrict__ f) {
    prep_rows(f, g_fb, g_rowterm, 2.0f * EPSV, EPSV * EPSV * (float)DD);
}
__global__ void __launch_bounds__(256) prep_centers_kernel(const float* __restrict__ c) {
    prep_rows(c, g_cb, g_centerterm, -2.0f * EPSV, 0.0f);
}

// ---------------- init + labels dtype detect ------------------------------------
__global__ void detect_init_kernel(const unsigned int* __restrict__ lw) {
    int i = blockIdx.x * blockDim.x + threadIdx.x;
    g_minmap[i] = 0x7F800000;
    if ((i & 1) && lw[i] != 0u) atomicOr(&g_odd_nonzero, 1);
}

// ---------------- GEMM + min epilogue --------------------------------------------
// CTA tile 128(M) x 128(N), BK=64, 3-stage cp.async pipeline, 2 CTAs/SM.
// 4 warps: 2(m) x 2(n), warp tile 64x64. SW128 swizzled smem (128B rows).
#define BM 128
#define BN 128
#define BK 64
#define NK (DD / BK)            // 16
#define A_BYTES (BM * BK * 2)   // 16384
#define B_BYTES (BN * BK * 2)   // 16384
#define STAGE_BYTES (A_BYTES + B_BYTES)
#define STAGES 3
#define GEMM_SMEM (STAGES * STAGE_BYTES + 512 + 16)
#define NTHREADS 128

// swizzled byte offset for (row, kbyte) in a 128B-row tile
__device__ __forceinline__ uint32_t swz(int r, int kbyte) {
    return (uint32_t)(r * 128 + (((kbyte >> 4) ^ (r & 7)) << 4) + (kbyte & 15));
}

__global__ void __launch_bounds__(NTHREADS, 2) gemm_min_kernel() {
    extern __shared__ char sm_raw[];
    char* smb = sm_raw;
    float* cterm = (float*)(sm_raw + STAGES * STAGE_BYTES);  // 128 floats

    const int tid  = threadIdx.x;
    const int lane = tid & 31;
    const int wid  = tid >> 5;       // 0..3
    const int wm   = wid >> 1;       // 0..1
    const int wn   = wid & 1;        // 0..1
    const int brow = blockIdx.y * BM;
    const int bcol = blockIdx.x * BN;

    const __nv_bfloat16* Ag = g_fb + (size_t)brow * DD;
    const __nv_bfloat16* Bg = g_cb + (size_t)bcol * DD;

    cterm[tid] = g_centerterm[bcol + tid];

    float acc[4][8][4];   // mt x nt x 4   (warp tile 64x64)
    #pragma unroll
    for (int mt = 0; mt < 4; mt++)
        #pragma unroll
        for (int nt = 0; nt < 8; nt++)
            #pragma unroll
            for (int j = 0; j < 4; j++) acc[mt][nt][j] = 0.f;

    // stage loader: A 1024 + B 1024 chunks of 16B, 16 per thread
    auto stage = [&](int kt, int buf) {
        int k0 = kt * BK;
        char* As = smb + buf * STAGE_BYTES;
        char* Bs = As + A_BYTES;
        #pragma unroll
        for (int i = 0; i < 8; i++) {
            int idx = tid + i * NTHREADS;
            int r = idx >> 3, c = idx & 7;
            cp16(As + swz(r, c * 16), Ag + (size_t)r * DD + k0 + c * 8);
        }
        #pragma unroll
        for (int i = 0; i < 8; i++) {
            int idx = tid + i * NTHREADS;
            int r = idx >> 3, c = idx & 7;
            cp16(Bs + swz(r, c * 16), Bg + (size_t)r * DD + k0 + c * 8);
        }
        cp_commit();
    };

    stage(0, 0);
    stage(1, 1);

    for (int kt = 0; kt < NK; kt++) {
        if (kt < NK - 1) cp_wait<1>(); else cp_wait<0>();
        __syncthreads();
        if (kt + 2 < NK) stage(kt + 2, (kt + 2) % STAGES);

        char* As = smb + (kt % STAGES) * STAGE_BYTES;
        char* Bs = As + A_BYTES;

        #pragma unroll
        for (int ks = 0; ks < 4; ks++) {   // 4 x k16
            uint32_t a[4][4];
            #pragma unroll
            for (int mt = 0; mt < 4; mt++) {
                int r = wm * 64 + mt * 16 + (lane & 15);
                int kbyte = ks * 32 + ((lane >> 4) << 4);
                ldm_x4(a[mt], As + swz(r, kbyte));
            }
            uint32_t b[4][4];
            #pragma unroll
            for (int p = 0; p < 4; p++) {
                int r = wn * 64 + p * 16 + (lane & 7) + ((lane & 16) >> 1);
                int kbyte = ks * 32 + (((lane >> 3) & 1) << 4);
                ldm_x4(b[p], Bs + swz(r, kbyte));
            }
            #pragma unroll
            for (int mt = 0; mt < 4; mt++)
                #pragma unroll
                for (int p = 0; p < 4; p++) {
                    mma16816(acc[mt][2 * p],     a[mt], b[p][0], b[p][1]);
                    mma16816(acc[mt][2 * p + 1], a[mt], b[p][2], b[p][3]);
                }
        }
    }

    // ---- epilogue: min over this CTA's 128 columns of (centerterm - 2*S) ----
    const float* ct = cterm + wn * 64;
    #pragma unroll
    for (int mt = 0; mt < 4; mt++) {
        float m0 = 1e30f, m1 = 1e30f;
        #pragma unroll
        for (int nt = 0; nt < 8; nt++) {
            float c0 = ct[nt * 8 + (lane & 3) * 2];
            float c1 = ct[nt * 8 + (lane & 3) * 2 + 1];
            m0 = fminf(m0, fminf(fmaf(-2.f, acc[mt][nt][0], c0),
                                 fmaf(-2.f, acc[mt][nt][1], c1)));
            m1 = fminf(m1, fminf(fmaf(-2.f, acc[mt][nt][2], c0),
                                 fmaf(-2.f, acc[mt][nt][3], c1)));
        }
        #pragma unroll
        for (int off = 1; off < 4; off <<= 1) {
            m0 = fminf(m0, __shfl_xor_sync(0xffffffff, m0, off));
            m1 = fminf(m1, __shfl_xor_sync(0xffffffff, m1, off));
        }
        if ((lane & 3) == 0) {
            int r = brow + wm * 64 + mt * 16 + (lane >> 2);
            atomicMin(&g_minmap[r],     fmap(m0));
            atomicMin(&g_minmap[r + 8], fmap(m1));
        }
    }
}

// ---------------- masked reduction ------------------------------------------------
__global__ void reduce_kernel(const void* __restrict__ labels) {
    int b   = blockIdx.x;
    int row = b * 256 + threadIdx.x;

    float m    = funmap(g_minmap[row]);
    float sq   = g_rowterm[row] + m;
    float dist = sqrtf(fmaxf(sq, 0.f));

    long long lab;
    if (g_odd_nonzero == 0) lab = ((const long long*)labels)[row];   // int64
    else                    lab = ((const int*)labels)[row];         // int32
    float mask = (lab == 0) ? 1.f : 0.f;

    float s = dist * mask;
    float c = mask;
    #pragma unroll
    for (int off = 16; off; off >>= 1) {
        s += __shfl_xor_sync(0xffffffff, s, off);
        c += __shfl_xor_sync(0xffffffff, c, off);
    }
    __shared__ float sh[2][8];
    int w = threadIdx.x >> 5, l = threadIdx.x & 31;
    if (l == 0) { sh[0][w] = s; sh[1][w] = c; }
    __syncthreads();
    if (threadIdx.x == 0) {
        float ts = 0.f, tc = 0.f;
        #pragma unroll
        for (int i = 0; i < 8; i++) { ts += sh[0][i]; tc += sh[1][i]; }
        g_psum[b] = ts;
        g_pcnt[b] = tc;
    }
}

__global__ void final_kernel(float* __restrict__ out) {
    int t = threadIdx.x;
    float s = g_psum[t] + g_psum[t + 32];
    float c = g_pcnt[t] + g_pcnt[t + 32];
    #pragma unroll
    for (int off = 16; off; off >>= 1) {
        s += __shfl_xor_sync(0xffffffff, s, off);
        c += __shfl_xor_sync(0xffffffff, c, off);
    }
    if (t == 0) out[0] = s / (c + DEN_EPS);
}

// ---------------- launch -------------------------------------------------------------
extern "C" void kernel_launch(void* const* d_in, const int* in_sizes, int n_in,
                              void* d_out, int out_size) {
    const float* features = (const float*)d_in[0];
    const void*  labels   = d_in[1];
    const float* centers  = (const float*)d_in[2];
    float* out = (float*)d_out;

    cudaFuncSetAttribute(gemm_min_kernel,
                         cudaFuncAttributeMaxDynamicSharedMemorySize, GEMM_SMEM);

    detect_init_kernel<<<64, 256>>>((const unsigned int*)labels);
    prep_features_kernel<<<NN / 8, 256>>>(features);
    prep_centers_kernel<<<CC / 8, 256>>>(centers);
    gemm_min_kernel<<<dim3(CC / BN, NN / BM), NTHREADS, GEMM_SMEM>>>();
    reduce_kernel<<<64, 256>>>(labels);
    final_kernel<<<1, 32>>>(out);
}

// round 6
// speedup vs baseline: 1.3801x; 1.0637x over previous
#include <cuda_runtime.h>
#include <cuda_bf16.h>
#include <cstdint>

// Problem constants
#define NN 16384
#define DD 1024
#define CC 1024
#define EPSV 1e-6f
#define DEN_EPS 1e-5f

// ---------------- device scratch ---------------------------------------------
__device__ __align__(1024) __nv_bfloat16 g_fb[NN * DD];   // features bf16 (32MB)
__device__ __align__(1024) __nv_bfloat16 g_cb[CC * DD];   // centers  bf16 ( 2MB)
__device__ float g_rowterm[NN];
__device__ float g_centerterm[CC];
__device__ int   g_minmap[NN];
__device__ int   g_odd_nonzero = 0;

// ---------------- helpers -------------------------------------------------------
__device__ __forceinline__ int fmap(float f) {
    int i = __float_as_int(f);
    return i >= 0 ? i : (i ^ 0x7FFFFFFF);
}
__device__ __forceinline__ float funmap(int i) {
    return __int_as_float(i >= 0 ? i : (i ^ 0x7FFFFFFF));
}

__device__ __forceinline__ void cp16(void* dst, const void* src) {
    unsigned d = (unsigned)__cvta_generic_to_shared(dst);
    asm volatile("cp.async.cg.shared.global [%0], [%1], 16;\n" :: "r"(d), "l"(src) : "memory");
}
__device__ __forceinline__ void cp_commit() {
    asm volatile("cp.async.commit_group;\n" ::: "memory");
}
template <int N>
__device__ __forceinline__ void cp_wait() {
    asm volatile("cp.async.wait_group %0;\n" :: "n"(N) : "memory");
}

__device__ __forceinline__ void ldm_x4(uint32_t* r, uint32_t saddr) {
    asm volatile("ldmatrix.sync.aligned.m8n8.x4.shared.b16 {%0,%1,%2,%3}, [%4];\n"
                 : "=r"(r[0]), "=r"(r[1]), "=r"(r[2]), "=r"(r[3]) : "r"(saddr));
}

__device__ __forceinline__ void mma16816(float* c, const uint32_t* a,
                                         uint32_t b0, uint32_t b1) {
    asm volatile(
        "mma.sync.aligned.m16n8k16.row.col.f32.bf16.bf16.f32 "
        "{%0,%1,%2,%3}, {%4,%5,%6,%7}, {%8,%9}, {%0,%1,%2,%3};\n"
        : "+f"(c[0]), "+f"(c[1]), "+f"(c[2]), "+f"(c[3])
        : "r"(a[0]), "r"(a[1]), "r"(a[2]), "r"(a[3]), "r"(b0), "r"(b1));
}

// ---------------- fused prologue ------------------------------------------------
// blocks [0,2048): features 8 rows each; [2048,2176): centers 8 rows each;
// [2176,2240): minmap init + labels dtype detect.
__device__ __forceinline__ void prep_rows(const float* __restrict__ src,
                                          __nv_bfloat16* dst, float* term,
                                          int blk, float coef, float add) {
    int wid  = threadIdx.x >> 5;
    int lane = threadIdx.x & 31;
    int row  = blk * 8 + wid;

    const float4* s4 = reinterpret_cast<const float4*>(src + (size_t)row * DD);
    uint2* d2 = reinterpret_cast<uint2*>(dst + (size_t)row * DD);

    float s = 0.f, s2 = 0.f;
    #pragma unroll
    for (int i = 0; i < 8; i++) {
        float4 v = s4[i * 32 + lane];
        __nv_bfloat162 lo = __floats2bfloat162_rn(v.x, v.y);
        __nv_bfloat162 hi = __floats2bfloat162_rn(v.z, v.w);
        uint2 packed;
        packed.x = *reinterpret_cast<uint32_t*>(&lo);
        packed.y = *reinterpret_cast<uint32_t*>(&hi);
        d2[i * 32 + lane] = packed;
        s  += v.x + v.y + v.z + v.w;
        s2 += v.x * v.x + v.y * v.y + v.z * v.z + v.w * v.w;
    }
    #pragma unroll
    for (int off = 16; off; off >>= 1) {
        s  += __shfl_xor_sync(0xffffffff, s,  off);
        s2 += __shfl_xor_sync(0xffffffff, s2, off);
    }
    if (lane == 0) term[row] = s2 + coef * s + add;
}

__global__ void __launch_bounds__(256) prologue_kernel(
        const float* __restrict__ f, const float* __restrict__ c,
        const unsigned int* __restrict__ lw) {
    int b = blockIdx.x;
    if (b < 2048) {
        prep_rows(f, g_fb, g_rowterm, b, 2.0f * EPSV, EPSV * EPSV * (float)DD);
    } else if (b < 2176) {
        prep_rows(c, g_cb, g_centerterm, b - 2048, -2.0f * EPSV, 0.0f);
    } else {
        int i = (b - 2176) * 256 + threadIdx.x;   // [0, 16384)
        g_minmap[i] = 0x7F800000;                 // fmap(+inf)
        if ((i & 1) && lw[i] != 0u) atomicOr(&g_odd_nonzero, 1);
    }
}

// ---------------- GEMM + min epilogue --------------------------------------------
// CTA tile 128x128, BK=64, 3-stage cp.async pipeline, 2 CTAs/SM.
// 4 warps: 2(m) x 2(n), warp tile 64x64. SW128 swizzled smem (128B rows).
#define BM 128
#define BN 128
#define BK 64
#define NK (DD / BK)            // 16
#define A_BYTES (BM * BK * 2)   // 16384
#define B_BYTES (BN * BK * 2)   // 16384
#define STAGE_BYTES (A_BYTES + B_BYTES)
#define STAGES 3
#define GEMM_SMEM (STAGES * STAGE_BYTES + 512 + 16)
#define NTHREADS 128

// swizzled byte offset for (row, kbyte) — loader-side (not hot)
__device__ __forceinline__ uint32_t swz(int r, int kbyte) {
    return (uint32_t)(r * 128 + (((kbyte >> 4) ^ (r & 7)) << 4) + (kbyte & 15));
}

__global__ void __launch_bounds__(NTHREADS, 2) gemm_min_kernel() {
    extern __shared__ char sm_raw[];
    char* smb = sm_raw;
    float* cterm = (float*)(sm_raw + STAGES * STAGE_BYTES);  // 128 floats

    const int tid  = threadIdx.x;
    const int lane = tid & 31;
    const int wid  = tid >> 5;       // 0..3
    const int wm   = wid >> 1;       // 0..1
    const int wn   = wid & 1;        // 0..1
    const int brow = blockIdx.y * BM;
    const int bcol = blockIdx.x * BN;

    const __nv_bfloat16* Ag = g_fb + (size_t)brow * DD;
    const __nv_bfloat16* Bg = g_cb + (size_t)bcol * DD;

    cterm[tid] = g_centerterm[bcol + tid];

    const uint32_t smem0 = (uint32_t)__cvta_generic_to_shared(smb);

    // ---- XOR-folded LDSM base offsets (within a stage tile) ----
    // addr(r, k16) = (r*128 | ((r&7)<<4)) ^ (k16<<4), carry-free.
    uint32_t aB[4], bB[4];
    {
        uint32_t hi16 = ((lane >> 4) & 1) << 4;        // A: k16 low bit
        #pragma unroll
        for (int mt = 0; mt < 4; mt++) {
            int r = wm * 64 + mt * 16 + (lane & 15);
            aB[mt] = ((uint32_t)(r * 128) | (uint32_t)((r & 7) << 4)) ^ hi16;
        }
        uint32_t hib = ((lane >> 3) & 1) << 4;         // B: k16 low bit
        #pragma unroll
        for (int p = 0; p < 4; p++) {
            int r = wn * 64 + p * 16 + (lane & 7) + ((lane & 16) >> 1);
            bB[p] = ((uint32_t)(r * 128) | (uint32_t)((r & 7) << 4)) ^ hib;
        }
    }

    float acc[4][8][4];   // mt x nt x 4   (warp tile 64x64)
    #pragma unroll
    for (int mt = 0; mt < 4; mt++)
        #pragma unroll
        for (int nt = 0; nt < 8; nt++)
            #pragma unroll
            for (int j = 0; j < 4; j++) acc[mt][nt][j] = 0.f;

    // stage loader: A 1024 + B 1024 chunks of 16B, 16 per thread
    auto stage = [&](int kt, int buf) {
        int k0 = kt * BK;
        char* As = smb + buf * STAGE_BYTES;
        char* Bs = As + A_BYTES;
        #pragma unroll
        for (int i = 0; i < 8; i++) {
            int idx = tid + i * NTHREADS;
            int r = idx >> 3, c = idx & 7;
            cp16(As + swz(r, c * 16), Ag + (size_t)r * DD + k0 + c * 8);
        }
        #pragma unroll
        for (int i = 0; i < 8; i++) {
            int idx = tid + i * NTHREADS;
            int r = idx >> 3, c = idx & 7;
            cp16(Bs + swz(r, c * 16), Bg + (size_t)r * DD + k0 + c * 8);
        }
        cp_commit();
    };

    stage(0, 0);
    stage(1, 1);

    for (int kt = 0; kt < NK; kt++) {
        if (kt < NK - 1) cp_wait<1>(); else cp_wait<0>();
        __syncthreads();

        const uint32_t a_base = smem0 + (uint32_t)((kt % STAGES) * STAGE_BYTES);
        const uint32_t b_base = a_base + A_BYTES;

        // ks = 0: issue LDSMs first so the tensor pipe refills right after the barrier
        uint32_t a[4][4], b[4][4];
        #pragma unroll
        for (int mt = 0; mt < 4; mt++) ldm_x4(a[mt], a_base + (aB[mt] ^ 0u));
        #pragma unroll
        for (int p = 0; p < 4; p++)  ldm_x4(b[p],  b_base + (bB[p] ^ 0u));

        // prefetch next stage while ks0 MMAs run
        if (kt + 2 < NK) stage(kt + 2, (kt + 2) % STAGES);

        #pragma unroll
        for (int mt = 0; mt < 4; mt++)
            #pragma unroll
            for (int p = 0; p < 4; p++) {
                mma16816(acc[mt][2 * p],     a[mt], b[p][0], b[p][1]);
                mma16816(acc[mt][2 * p + 1], a[mt], b[p][2], b[p][3]);
            }

        #pragma unroll
        for (int ks = 1; ks < 4; ks++) {   // remaining k16 slices
            const uint32_t kx = (uint32_t)(ks * 32);
            #pragma unroll
            for (int mt = 0; mt < 4; mt++) ldm_x4(a[mt], a_base + (aB[mt] ^ kx));
            #pragma unroll
            for (int p = 0; p < 4; p++)  ldm_x4(b[p],  b_base + (bB[p] ^ kx));
            #pragma unroll
            for (int mt = 0; mt < 4; mt++)
                #pragma unroll
                for (int p = 0; p < 4; p++) {
                    mma16816(acc[mt][2 * p],     a[mt], b[p][0], b[p][1]);
                    mma16816(acc[mt][2 * p + 1], a[mt], b[p][2], b[p][3]);
                }
        }
    }

    // ---- epilogue: min over this CTA's 128 columns of (centerterm - 2*S) ----
    const float* ct = cterm + wn * 64;
    #pragma unroll
    for (int mt = 0; mt < 4; mt++) {
        float m0 = 1e30f, m1 = 1e30f;
        #pragma unroll
        for (int nt = 0; nt < 8; nt++) {
            float c0 = ct[nt * 8 + (lane & 3) * 2];
            float c1 = ct[nt * 8 + (lane & 3) * 2 + 1];
            m0 = fminf(m0, fminf(fmaf(-2.f, acc[mt][nt][0], c0),
                                 fmaf(-2.f, acc[mt][nt][1], c1)));
            m1 = fminf(m1, fminf(fmaf(-2.f, acc[mt][nt][2], c0),
                                 fmaf(-2.f, acc[mt][nt][3], c1)));
        }
        #pragma unroll
        for (int off = 1; off < 4; off <<= 1) {
            m0 = fminf(m0, __shfl_xor_sync(0xffffffff, m0, off));
            m1 = fminf(m1, __shfl_xor_sync(0xffffffff, m1, off));
        }
        if ((lane & 3) == 0) {
            int r = brow + wm * 64 + mt * 16 + (lane >> 2);
            atomicMin(&g_minmap[r],     fmap(m0));
            atomicMin(&g_minmap[r + 8], fmap(m1));
        }
    }
}

// ---------------- fused masked reduction (single block) ---------------------------
__global__ void __launch_bounds__(1024) reduce_final_kernel(
        const void* __restrict__ labels, float* __restrict__ out) {
    int tid = threadIdx.x;
    bool lab64 = (g_odd_nonzero == 0);

    float s = 0.f, c = 0.f;
    #pragma unroll
    for (int i = 0; i < 16; i++) {
        int row = tid + i * 1024;
        float m    = funmap(g_minmap[row]);
        float sq   = g_rowterm[row] + m;
        float dist = sqrtf(fmaxf(sq, 0.f));
        long long lab = lab64 ? ((const long long*)labels)[row]
                              : (long long)((const int*)labels)[row];
        if (lab == 0) { s += dist; c += 1.f; }
    }
    #pragma unroll
    for (int off = 16; off; off >>= 1) {
        s += __shfl_xor_sync(0xffffffff, s, off);
        c += __shfl_xor_sync(0xffffffff, c, off);
    }
    __shared__ float sh[2][32];
    int w = tid >> 5, l = tid & 31;
    if (l == 0) { sh[0][w] = s; sh[1][w] = c; }
    __syncthreads();
    if (w == 0) {
        float ts = sh[0][l], tc = sh[1][l];
        #pragma unroll
        for (int off = 16; off; off >>= 1) {
            ts += __shfl_xor_sync(0xffffffff, ts, off);
            tc += __shfl_xor_sync(0xffffffff, tc, off);
        }
        if (l == 0) out[0] = ts / (tc + DEN_EPS);
    }
}

// ---------------- launch -------------------------------------------------------------
extern "C" void kernel_launch(void* const* d_in, const int* in_sizes, int n_in,
                              void* d_out, int out_size) {
    const float* features = (const float*)d_in[0];
    const void*  labels   = d_in[1];
    const float* centers  = (const float*)d_in[2];
    float* out = (float*)d_out;

    cudaFuncSetAttribute(gemm_min_kernel,
                         cudaFuncAttributeMaxDynamicSharedMemorySize, GEMM_SMEM);

    prologue_kernel<<<2240, 256>>>(features, centers, (const unsigned int*)labels);
    gemm_min_kernel<<<dim3(CC / BN, NN / BM), NTHREADS, GEMM_SMEM>>>();
    reduce_final_kernel<<<1, 1024>>>(labels, out);
}